// round 17
// baseline (speedup 1.0000x reference)
#include <cuda_runtime.h>
#include <float.h>

#define N_  2
#define C_  256
#define H_  56
#define W_  56
#define R_  512
#define P_  7
#define SCALE_ 0.0625f
#define PLANE_ (H_ * W_)      // 3136
#define C4_    (C_ / 4)       // 64 float4 per cell

// NHWC tensors: [b][hw][c]
__device__ float g_t[(size_t)N_ * PLANE_ * C_];   // features
__device__ float g_2[(size_t)N_ * PLANE_ * C_];   // 2x2 pairmax (edge-clamped)

__device__ __forceinline__ float4 fmax4(float4 a, float4 b) {
    return make_float4(fmaxf(a.x,b.x), fmaxf(a.y,b.y), fmaxf(a.z,b.z), fmaxf(a.w,b.w));
}

// ---------- kernel 1: fused NCHW->NHWC transpose + 2x2 pairmax ----------
__global__ __launch_bounds__(256) void prep_kernel(const float* __restrict__ f)
{
    __shared__ float s[32 * 113];   // [c][row h | row hd]; stride 113 coprime with 32
    const int h  = blockIdx.x;
    const int c0 = blockIdx.y * 32;
    const int b  = blockIdx.z;
    const int hd = min(h + 1, H_ - 1);
    const int t  = threadIdx.x;

    for (int i = t; i < 32 * 112; i += 256) {
        int c = i / 112, j = i - c * 112;
        int row = (j < W_) ? h : hd;
        int w   = (j < W_) ? j : j - W_;
        s[c * 113 + j] = __ldg(f + ((size_t)b * C_ + c0 + c) * PLANE_ + row * W_ + w);
    }
    __syncthreads();

    for (int i = t; i < 32 * W_; i += 256) {
        int c = i & 31;
        int w = i >> 5;
        int wr = min(w + 1, W_ - 1);
        float a  = s[c * 113 + w];
        float r  = s[c * 113 + wr];
        float d  = s[c * 113 + W_ + w];
        float dr = s[c * 113 + W_ + wr];
        size_t o = ((size_t)b * PLANE_ + h * W_ + w) * C_ + c0 + c;
        g_t[o] = a;
        g_2[o] = fmaxf(fmaxf(a, r), fmaxf(d, dr));
    }
}

// ---------- kernel 2: pooling; overlapping-quad cover, batched loads ----------
__global__ __launch_bounds__(512, 4) void roipool_kernel(
    const float* __restrict__ rois,
    float* __restrict__ out)
{
    __shared__ int   sdesc[P_ * P_];
    __shared__ int   sb;
    __shared__ __align__(16) float stage[128 * P_ * P_];

    const int t    = threadIdx.x;
    const int lane = t & 31;
    const int wrp  = t >> 5;                   // 16 warps
    const int r    = blockIdx.x >> 1;
    const int c0q  = (blockIdx.x & 1) * 32;    // C-half in float4 units

    if (t < P_ * P_) {
        const float* roi = rois + r * 5;
        int x1 = __float2int_rn(roi[1] * SCALE_);   // half-even == jnp.round
        int y1 = __float2int_rn(roi[2] * SCALE_);
        int x2 = __float2int_rn(roi[3] * SCALE_);
        int y2 = __float2int_rn(roi[4] * SCALE_);
        float bin_h = (float)max(y2 - y1 + 1, 1) * (1.0f / P_);
        float bin_w = (float)max(x2 - x1 + 1, 1) * (1.0f / P_);

        int ph = t / P_, pw = t - ph * P_;
        int hs = min(max((int)floorf((float)ph       * bin_h) + y1, 0), H_);
        int he = min(max((int)ceilf ((float)(ph + 1) * bin_h) + y1, 0), H_);
        int ws = min(max((int)floorf((float)pw       * bin_w) + x1, 0), W_);
        int we = min(max((int)ceilf ((float)(pw + 1) * bin_w) + x1, 0), W_);

        int dh = max(he - hs, 0);
        int dw = max(we - ws, 0);
        sdesc[t] = (hs * W_ + ws) | (dh << 16) | (dw << 22);
        if (t == 0) sb = (int)roi[0];               // trunc == astype(int32)
    }
    __syncthreads();

    const int bP = sb * PLANE_;                     // warp-uniform
    const float4* t4 = (const float4*)g_t;
    const float4* q4 = (const float4*)g_2;

    for (int u = wrp; u < P_ * P_; u += 16) {
        int d    = sdesc[u];
        int base =  d        & 0xFFFF;
        int dh   = (d >> 16) & 0x3F;
        int dw   =  d >> 22;

        int o = (bP + base) * C4_ + c0q + lane;     // 32-bit float4 index

        float4 m = make_float4(-FLT_MAX, -FLT_MAX, -FLT_MAX, -FLT_MAX);

        if (dh >= 2 && dw >= 2) {
            // overlapping 2x2 quads at offsets {0, min(2,d-2), d-2}: full cover,
            // every quad inside the window (clamped g_2 edges never engaged).
            int nh = (dh + 1) >> 1, nw = (dw + 1) >> 1;         // <= 3
            int ro[3] = { 0, min(2, dh - 2) * (W_ * C4_), (dh - 2) * (W_ * C4_) };
            int co[3] = { 0, min(2, dw - 2) * C4_,        (dw - 2) * C4_        };
            // batch all loads first (one L2 round trip), then reduce
            float4 v[9];
            #pragma unroll
            for (int i = 0; i < 3; ++i)
                #pragma unroll
                for (int j = 0; j < 3; ++j)
                    if (i < nh && j < nw)
                        v[i * 3 + j] = __ldg(q4 + o + ro[i] + co[j]);
            #pragma unroll
            for (int i = 0; i < 3; ++i)
                #pragma unroll
                for (int j = 0; j < 3; ++j)
                    if (i < nh && j < nw)
                        m = fmax4(m, v[i * 3 + j]);
        } else if (dh > 0 && dw > 0) {
            // degenerate line (dh==1 or dw==1): <=5 raw cells from g_t
            int n    = dh * dw;                                  // == max(dh,dw)
            int step = (dh == 1) ? C4_ : W_ * C4_;
            float4 v[5];
            #pragma unroll
            for (int k = 0; k < 5; ++k)
                if (k < n) v[k] = __ldg(t4 + o + k * step);
            #pragma unroll
            for (int k = 0; k < 5; ++k)
                if (k < n) m = fmax4(m, v[k]);
        } else {
            m = make_float4(0.f, 0.f, 0.f, 0.f);
        }

        stage[(4 * lane + 0) * (P_ * P_) + u] = m.x;
        stage[(4 * lane + 1) * (P_ * P_) + u] = m.y;
        stage[(4 * lane + 2) * (P_ * P_) + u] = m.z;
        stage[(4 * lane + 3) * (P_ * P_) + u] = m.w;
    }
    __syncthreads();

    const size_t obase = ((size_t)r * C_ + c0q * 4) * (P_ * P_);
    const float4* s4 = (const float4*)stage;
    float4* o4 = (float4*)(out + obase);
    #pragma unroll
    for (int k = 0; k < (128 * P_ * P_ / 4 + 511) / 512; ++k) {
        int i = t + k * 512;
        if (i < 128 * P_ * P_ / 4) o4[i] = s4[i];
    }
}

extern "C" void kernel_launch(void* const* d_in, const int* in_sizes, int n_in,
                              void* d_out, int out_size)
{
    const float* features = (const float*)d_in[0];
    const float* rois     = (const float*)d_in[1];
    float* out            = (float*)d_out;

    dim3 pg(H_, C_ / 32, N_);                 // 56 x 8 x 2 = 896 blocks
    prep_kernel<<<pg, 256>>>(features);

    roipool_kernel<<<R_ * 2, 512>>>(rois, out);   // 1024 blocks
}